// round 12
// baseline (speedup 1.0000x reference)
#include <cuda_runtime.h>

#define B_  64
#define T_  2048
#define H_  128
#define N3  384
#define BT  (B_ * T_)
#define NCHUNK  32
#define SCAN_CTAS 64
#define GEMM_CTAS 84
#define GRID      (SCAN_CTAS + GEMM_CTAS)   // 148, all resident
#define NT 512

typedef unsigned long long ull;

// Scratch (allocation-free rule). g_gx padded one row for unconditional prefetch.
__device__ float g_gx  [(size_t)BT * N3 + N3];
__device__ float g_bufA[(size_t)BT * H_];
__device__ float g_bufB[(size_t)BT * H_];
__device__ int g_cnt[3][B_][NCHUNK];   // gx chunk counters (target 3 n-tiles)
__device__ int g_rdy[3][B_][NCHUNK];   // scan chunk-done flags

// ---------------- packed f32x2 helpers (register-only asm: safe) -----------
__device__ __forceinline__ ull pk2(float lo, float hi) {
    ull r; asm("mov.b64 %0,{%1,%2};" : "=l"(r) : "f"(lo), "f"(hi)); return r;
}
__device__ __forceinline__ ull ffma2(ull a, ull b, ull c) {
    ull d; asm("fma.rn.f32x2 %0,%1,%2,%3;" : "=l"(d) : "l"(a), "l"(b), "l"(c)); return d;
}
__device__ __forceinline__ float sum2(ull v) {
    float lo, hi; asm("mov.b64 {%0,%1},%2;" : "=f"(lo), "=f"(hi) : "l"(v));
    return lo + hi;
}
__device__ __forceinline__ void unpk2(ull v, float& lo, float& hi) {
    asm("mov.b64 {%0,%1},%2;" : "=f"(lo), "=f"(hi) : "l"(v));
}
__device__ __forceinline__ unsigned smem_u32(const void* p) {
    unsigned a;
    asm("{.reg .u64 u; cvta.to.shared.u64 u,%1; cvt.u32.u64 %0,u;}" : "=r"(a) : "l"(p));
    return a;
}
// Volatile explicit-shared ops: fast LDS/STS path, never hoisted across bars.
__device__ __forceinline__ void lds_v2u64(unsigned addr, ull& a, ull& b) {
    asm volatile("ld.shared.v2.u64 {%0,%1},[%2];" : "=l"(a), "=l"(b) : "r"(addr));
}
__device__ __forceinline__ void sts_f32(unsigned addr, float v) {
    asm volatile("st.shared.f32 [%0],%1;" :: "r"(addr), "f"(v));
}
// Coherent L2 loads for intra-kernel-produced data (.cg skips L1 -> no staleness).
__device__ __forceinline__ float ldg_cg(const float* p) {
    float v; asm volatile("ld.global.cg.f32 %0,[%1];" : "=f"(v) : "l"(p)); return v;
}
__device__ __forceinline__ float4 ldg_cg4(const float* p) {
    float4 v;
    asm volatile("ld.global.cg.v4.f32 {%0,%1,%2,%3},[%4];"
                 : "=f"(v.x), "=f"(v.y), "=f"(v.z), "=f"(v.w) : "l"(p));
    return v;
}
// Acquire/release flag ops
__device__ __forceinline__ int ld_acq(const int* p) {
    int v; asm volatile("ld.acquire.gpu.global.b32 %0,[%1];" : "=r"(v) : "l"(p)); return v;
}
__device__ __forceinline__ void st_rel(int* p, int v) {
    asm volatile("st.release.gpu.global.b32 [%0],%1;" :: "l"(p), "r"(v) : "memory");
}
__device__ __forceinline__ void red_rel_add1(int* p) {
    asm volatile("red.release.gpu.global.add.s32 [%0],%1;" :: "l"(p), "r"(1) : "memory");
}

#define NLOG2E  (-1.442695040888963f)
#define N2LOG2E (-2.885390081777927f)

__device__ __forceinline__ float fsigmoid(float x) {
    float e = exp2f(fminf(x * NLOG2E, 126.f));
    return __fdividef(1.f, 1.f + e);
}

// ---------------------------------------------------------------------------
// GEMM tile (unchanged from R8): C[64,128] += A[64,128]@Bm + bias.
// tid<256 active; uniform barriers for all NT threads.
// ---------------------------------------------------------------------------
__device__ void gemm_tile(
    const float* A, const float* __restrict__ Bm,
    const float* __restrict__ bias, float* __restrict__ C,
    int N, int m0, int n0, int applySigmoid,
    float (*sA)[33], float (*sB)[128])
{
    const int tid = threadIdx.x;
    const bool act = tid < 256;
    const int tx = tid & 15;
    const int ty = (tid >> 4) & 15;
    const int arow = (tid >> 3) & 31;
    const int akq  = tid & 7;
    const int brow = (tid >> 5) & 7;
    const int bcol = tid & 31;
    const unsigned sb_base = smem_u32(&sB[0][0]) + tx * 32;

    ull acc2[4][4];
    #pragma unroll
    for (int i = 0; i < 4; i++)
        #pragma unroll
        for (int j = 0; j < 4; j++) acc2[i][j] = 0ULL;

    for (int k0 = 0; k0 < 128; k0 += 32) {
        float4 a0, a1, b0, b1, b2, b3;
        if (act) {
            a0 = ldg_cg4(A + (size_t)(m0 + arow     ) * H_ + k0 + akq * 4);
            a1 = ldg_cg4(A + (size_t)(m0 + arow + 32) * H_ + k0 + akq * 4);
            b0 = *(const float4*)(Bm + (size_t)(k0 + brow     ) * N + n0 + bcol * 4);
            b1 = *(const float4*)(Bm + (size_t)(k0 + brow +  8) * N + n0 + bcol * 4);
            b2 = *(const float4*)(Bm + (size_t)(k0 + brow + 16) * N + n0 + bcol * 4);
            b3 = *(const float4*)(Bm + (size_t)(k0 + brow + 24) * N + n0 + bcol * 4);
        }
        __syncthreads();
        if (act) {
            sA[arow     ][akq * 4 + 0] = a0.x;  sA[arow     ][akq * 4 + 1] = a0.y;
            sA[arow     ][akq * 4 + 2] = a0.z;  sA[arow     ][akq * 4 + 3] = a0.w;
            sA[arow + 32][akq * 4 + 0] = a1.x;  sA[arow + 32][akq * 4 + 1] = a1.y;
            sA[arow + 32][akq * 4 + 2] = a1.z;  sA[arow + 32][akq * 4 + 3] = a1.w;
            *(float4*)&sB[brow     ][bcol * 4] = b0;
            *(float4*)&sB[brow +  8][bcol * 4] = b1;
            *(float4*)&sB[brow + 16][bcol * 4] = b2;
            *(float4*)&sB[brow + 24][bcol * 4] = b3;
        }
        __syncthreads();
        if (act) {
            #pragma unroll
            for (int k = 0; k < 32; k++) {
                ull pa[4];
                #pragma unroll
                for (int i = 0; i < 4; i++) {
                    float a = sA[ty * 4 + i][k];
                    pa[i] = pk2(a, a);
                }
                ull b01, b23, b45, b67;
                lds_v2u64(sb_base + k * 512,      b01, b23);
                lds_v2u64(sb_base + k * 512 + 16, b45, b67);
                #pragma unroll
                for (int i = 0; i < 4; i++) {
                    acc2[i][0] = ffma2(pa[i], b01, acc2[i][0]);
                    acc2[i][1] = ffma2(pa[i], b23, acc2[i][1]);
                    acc2[i][2] = ffma2(pa[i], b45, acc2[i][2]);
                    acc2[i][3] = ffma2(pa[i], b67, acc2[i][3]);
                }
            }
        }
    }

    if (act) {
        float bs[8];
        #pragma unroll
        for (int j = 0; j < 8; j++) bs[j] = bias[n0 + tx * 8 + j];
        #pragma unroll
        for (int i = 0; i < 4; i++) {
            const int row = m0 + ty * 4 + i;
            float v[8];
            #pragma unroll
            for (int j = 0; j < 4; j++) unpk2(acc2[i][j], v[2 * j], v[2 * j + 1]);
            #pragma unroll
            for (int j = 0; j < 8; j++) {
                float x = v[j] + bs[j];
                v[j] = applySigmoid ? fsigmoid(x) : x;
            }
            float4 o0 = {v[0], v[1], v[2], v[3]};
            float4 o1 = {v[4], v[5], v[6], v[7]};
            *(float4*)(C + (size_t)row * N + n0 + tx * 8    ) = o0;
            *(float4*)(C + (size_t)row * N + n0 + tx * 8 + 4) = o1;
        }
    }
}

__device__ __forceinline__ void wait_flag(const int* p, int target) {
    if (threadIdx.x == 0) {
        while (ld_acq(p) < target) __nanosleep(128);
    }
    __syncthreads();
}

__global__ void init_flags() {
    const int n = 3 * B_ * NCHUNK;
    int* a = &g_cnt[0][0][0];
    int* b = &g_rdy[0][0][0];
    for (int i = threadIdx.x; i < n; i += blockDim.x) { a[i] = 0; b[i] = 0; }
}

// ---------------------------------------------------------------------------
// Mega-kernel. Scan CTA (512 thr): group g=tid>>2 owns hidden unit g; class
// c=tid&3 covers tape floats [96c,96c+96) of the concatenated [z|r|h] k-tape.
// Tape physical layout skewed: P(f)=f+4*(f/96) -> conflict-free class loads.
// Double-buffered tape kills the read/write hazard; gates exchanged by shfl.
// ONE __syncthreads per step.
// ---------------------------------------------------------------------------
__global__ void __launch_bounds__(NT, 1) mega(
    const float* __restrict__ X,
    const float* __restrict__ kern,
    const float* __restrict__ rec,
    const float* __restrict__ b_in,
    const float* __restrict__ b_rec,
    const float* __restrict__ W_out,
    const float* __restrict__ b_out,
    float*       __restrict__ out)
{
    __shared__ __align__(16) float tp[2][400];
    __shared__ __align__(16) float ring[64][128];
    __shared__ float sA[64][33];
    __shared__ __align__(16) float sB[32][128];

    const int cta = blockIdx.x;
    const int t   = threadIdx.x;

    if (cta < SCAN_CTAS) {
        const int b   = cta;
        const int g   = t >> 2;     // hidden unit 0..127
        const int cls = t & 3;      // tape class
        const int lb  = (t & 31) & ~3;  // group base lane within warp

        // Weights: tape floats [96*cls, 96*cls+96) -> 48 ull regs.
        ull w2[48];
        #pragma unroll
        for (int j2 = 0; j2 < 48; j2++) {
            const int f = 96 * cls + 2 * j2;
            const int k = f & 127;
            const int col = (f >> 7) * 128 + g;
            w2[j2] = pk2(rec[k * N3 + col], rec[(k + 1) * N3 + col]);
        }
        const int colc = (cls < 2 ? cls : 2) * 128 + g;   // this lane's gate column
        const float brec = b_rec[colc];

        // Tape write slots for h_g (lane cls==2 writes h to 3 virtual spots).
        const unsigned tbase = smem_u32(&tp[0][0]);
        unsigned wo0 = 0, wo1 = 0, wo2 = 0;
        {
            int f0 = g, f1 = 128 + g, f2 = 256 + g;
            wo0 = (unsigned)(f0 + 4 * (f0 / 96)) * 4u;
            wo1 = (unsigned)(f1 + 4 * (f1 / 96)) * 4u;
            wo2 = (unsigned)(f2 + 4 * (f2 / 96)) * 4u;
        }
        const unsigned rdoff = 400u * cls;   // bytes: 100*cls floats

        for (int l = 0; l < 3; l++) {
            float* ybase = ((l == 1) ? g_bufB : g_bufA) + (size_t)b * T_ * H_;
            const float* gxp = g_gx + (size_t)b * T_ * N3 + colc;

            if (t < 400) { tp[0][t] = 0.f; tp[1][t] = 0.f; }
            if (t == 0) {
                while (ld_acq(&g_cnt[l][b][0]) < 3) __nanosleep(128);
                while (ld_acq(&g_cnt[l][b][1]) < 3) __nanosleep(128);
            }
            float h_old = 0.f;
            int par = 0;
            __syncthreads();

            float gxv = ldg_cg(gxp);

            for (int step = 0; step < T_; ++step) {
                if ((step & 63) == 0 && step) {
                    const int c  = step >> 6;
                    const int c2 = (c + 1 < NCHUNK) ? c + 1 : NCHUNK - 1;
                    if (t == 0) {
                        while (ld_acq(&g_cnt[l][b][c ]) < 3) __nanosleep(64);
                        while (ld_acq(&g_cnt[l][b][c2]) < 3) __nanosleep(64);
                    }
                    __syncthreads();
                }

                float gxn = ldg_cg(gxp + (size_t)(step + 1) * N3);

                // ---- dot: 24 LDS.128 + 48 FFMA2 into 3 segment accs ----
                const unsigned rb = tbase + (unsigned)par * 1600u + rdoff;
                ull A = 0ULL, Bv = 0ULL, C = 0ULL;
                #pragma unroll
                for (int jl = 0; jl < 8; jl++) {
                    ull h0, h1;
                    lds_v2u64(rb + 16u * jl, h0, h1);
                    A = ffma2(h0, w2[2 * jl    ], A);
                    A = ffma2(h1, w2[2 * jl + 1], A);
                }
                #pragma unroll
                for (int jl = 8; jl < 16; jl++) {
                    ull h0, h1;
                    lds_v2u64(rb + 16u * jl, h0, h1);
                    Bv = ffma2(h0, w2[2 * jl    ], Bv);
                    Bv = ffma2(h1, w2[2 * jl + 1], Bv);
                }
                #pragma unroll
                for (int jl = 16; jl < 24; jl++) {
                    ull h0, h1;
                    lds_v2u64(rb + 16u * jl, h0, h1);
                    C = ffma2(h0, w2[2 * jl    ], C);
                    C = ffma2(h1, w2[2 * jl + 1], C);
                }
                const float a  = sum2(A);
                const float bb = sum2(Bv);
                const float cc = sum2(C);
                const float u  = a + bb + cc;

                // ---- combine partials across the 4-lane group ----
                const float nA  = __shfl_down_sync(0xffffffffu, a, 1);
                const float nAB = __shfl_down_sync(0xffffffffu, a + bb, 1);
                const float nU  = __shfl_down_sync(0xffffffffu, u, 1);
                // gate totals valid in lanes: cls0 -> z, cls1 -> r, cls2 -> hh
                float tot;
                if (cls == 0)      tot = u + nA;
                else if (cls == 1) tot = (bb + cc) + nAB;
                else               tot = cc + nU;

                // cls 0/1: sigmoid(gx + gate + bias); cls 2: hh + brec (raw)
                const float pre = (cls == 2) ? (tot + brec) : (gxv + tot + brec);
                const float sig = fsigmoid(pre);

                const float zv = __shfl_sync(0xffffffffu, sig, lb + 0, 32);
                const float rv = __shfl_sync(0xffffffffu, sig, lb + 1, 32);

                if (cls == 2) {
                    // cand = tanh(gx_h + r*(hh+brh));  pre == hh+brh, gxv == gx_h
                    float arg = fminf(fmaf(rv, pre * N2LOG2E, gxv * N2LOG2E), 126.f);
                    float cnd = __fdividef(2.f, 1.f + exp2f(arg)) - 1.f;
                    float hn  = fmaf(zv, h_old - cnd, cnd);
                    h_old = hn;
                    const unsigned wb = tbase + (unsigned)(1 - par) * 1600u;
                    sts_f32(wb + wo0, hn);
                    sts_f32(wb + wo1, hn);
                    sts_f32(wb + wo2, hn);
                    ring[step & 63][g] = hn;
                }
                __syncthreads();
                par ^= 1;
                gxv = gxn;

                if ((step & 63) == 63) {   // flush chunk + publish
                    const int c = step >> 6;
                    float* dst = ybase + (size_t)c * 64 * H_;
                    #pragma unroll
                    for (int q = 0; q < 4; q++) {
                        const int idx = t + q * NT;   // 2048 float4s
                        float4 v = *(const float4*)&ring[idx >> 5][(idx & 31) * 4];
                        *(float4*)(dst + idx * 4) = v;
                    }
                    __threadfence();
                    __syncthreads();
                    if (t == 0) st_rel(&g_rdy[l][b][c], 1);
                }
            }
        }
    } else {
        // ================= GEMM worker (R8 scheme) =========================
        const int wrk = cta - SCAN_CTAS;

        for (int l = 0; l < 3; l++) {
            const float* Asrc = (l == 0) ? X : ((l == 1) ? g_bufA : g_bufB);
            for (int idx = wrk; idx < NCHUNK * B_ * 3; idx += GEMM_CTAS) {
                const int c = idx / (B_ * 3);
                const int r = idx % (B_ * 3);
                const int b = r / 3;
                const int n = r % 3;
                if (l > 0) wait_flag(&g_rdy[l - 1][b][c], 1);
                gemm_tile(Asrc, kern, b_in, g_gx, N3,
                          b * T_ + c * 64, n * 128, 0, sA, sB);
                __threadfence();
                __syncthreads();
                if (t == 0) red_rel_add1(&g_cnt[l][b][c]);
            }
        }
        for (int idx = wrk; idx < NCHUNK * B_; idx += GEMM_CTAS) {
            const int c = idx / B_;
            const int b = idx % B_;
            wait_flag(&g_rdy[2][b][c], 1);
            gemm_tile(g_bufA, W_out, b_out, out, H_,
                      b * T_ + c * 64, 0, 1, sA, sB);
        }
    }
}

// ---------------------------------------------------------------------------
extern "C" void kernel_launch(void* const* d_in, const int* in_sizes, int n_in,
                              void* d_out, int out_size)
{
    const float* X     = (const float*)d_in[0];
    const float* kern  = (const float*)d_in[1];
    const float* rec   = (const float*)d_in[2];
    const float* b_in  = (const float*)d_in[3];
    const float* b_rec = (const float*)d_in[4];
    const float* W_out = (const float*)d_in[5];
    const float* b_out = (const float*)d_in[6];
    float* out = (float*)d_out;

    init_flags<<<1, 256>>>();
    mega<<<GRID, NT>>>(X, kern, rec, b_in, b_rec, W_out, b_out, out);
}

// round 13
// speedup vs baseline: 1.7026x; 1.7026x over previous
#include <cuda_runtime.h>

#define B_  64
#define T_  2048
#define H_  128
#define N3  384
#define BT  (B_ * T_)
#define NCHUNK  32
#define SCAN_CTAS 64
#define GEMM_CTAS 84
#define GRID      (SCAN_CTAS + GEMM_CTAS)   // 148, all resident
#define NT 256

typedef unsigned long long ull;

// Scratch (allocation-free rule). g_gx padded one row for unconditional prefetch.
__device__ float g_gx  [(size_t)BT * N3 + N3];
__device__ float g_bufA[(size_t)BT * H_];
__device__ float g_bufB[(size_t)BT * H_];
__device__ int g_cnt[3][B_][NCHUNK];   // gx chunk counters (target 3 n-tiles)
__device__ int g_rdy[3][B_][NCHUNK];   // scan chunk-done flags

// ---------------- packed f32x2 helpers (register-only asm: safe) -----------
__device__ __forceinline__ ull pk2(float lo, float hi) {
    ull r; asm("mov.b64 %0,{%1,%2};" : "=l"(r) : "f"(lo), "f"(hi)); return r;
}
__device__ __forceinline__ ull ffma2(ull a, ull b, ull c) {
    ull d; asm("fma.rn.f32x2 %0,%1,%2,%3;" : "=l"(d) : "l"(a), "l"(b), "l"(c)); return d;
}
__device__ __forceinline__ float sum2(ull v) {
    float lo, hi; asm("mov.b64 {%0,%1},%2;" : "=f"(lo), "=f"(hi) : "l"(v));
    return lo + hi;
}
__device__ __forceinline__ void unpk2(ull v, float& lo, float& hi) {
    asm("mov.b64 {%0,%1},%2;" : "=f"(lo), "=f"(hi) : "l"(v));
}
__device__ __forceinline__ unsigned smem_u32(const void* p) {
    unsigned a;
    asm("{.reg .u64 u; cvta.to.shared.u64 u,%1; cvt.u32.u64 %0,u;}" : "=r"(a) : "l"(p));
    return a;
}
// Volatile explicit-shared ops: fast LDS/STS path, never hoisted across bars.
__device__ __forceinline__ void lds_v2u64(unsigned addr, ull& a, ull& b) {
    asm volatile("ld.shared.v2.u64 {%0,%1},[%2];" : "=l"(a), "=l"(b) : "r"(addr));
}
__device__ __forceinline__ void lds_u64(unsigned addr, ull& a) {
    asm volatile("ld.shared.u64 %0,[%1];" : "=l"(a) : "r"(addr));
}
__device__ __forceinline__ void sts_f32(unsigned addr, float v) {
    asm volatile("st.shared.f32 [%0],%1;" :: "r"(addr), "f"(v));
}
// Coherent L2 loads for intra-kernel-produced data (.cg skips L1 -> no staleness).
__device__ __forceinline__ float ldg_cg(const float* p) {
    float v; asm volatile("ld.global.cg.f32 %0,[%1];" : "=f"(v) : "l"(p)); return v;
}
__device__ __forceinline__ float4 ldg_cg4(const float* p) {
    float4 v;
    asm volatile("ld.global.cg.v4.f32 {%0,%1,%2,%3},[%4];"
                 : "=f"(v.x), "=f"(v.y), "=f"(v.z), "=f"(v.w) : "l"(p));
    return v;
}
// Acquire/release flag ops
__device__ __forceinline__ int ld_acq(const int* p) {
    int v; asm volatile("ld.acquire.gpu.global.b32 %0,[%1];" : "=r"(v) : "l"(p)); return v;
}
__device__ __forceinline__ void st_rel(int* p, int v) {
    asm volatile("st.release.gpu.global.b32 [%0],%1;" :: "l"(p), "r"(v) : "memory");
}
__device__ __forceinline__ void red_rel_add1(int* p) {
    asm volatile("red.release.gpu.global.add.s32 [%0],%1;" :: "l"(p), "r"(1) : "memory");
}

#define NLOG2E  (-1.442695040888963f)
#define N2LOG2E (-2.885390081777927f)

__device__ __forceinline__ float fsigmoid(float x) {
    float e = exp2f(fminf(x * NLOG2E, 126.f));
    return __fdividef(1.f, 1.f + e);
}

// ---------------------------------------------------------------------------
// GEMM tile (proven R8 version): C[64,128] = A[64,128]@Bm + bias.
// 256 threads, uniform barriers.
// ---------------------------------------------------------------------------
__device__ void gemm_tile(
    const float* A, const float* __restrict__ Bm,
    const float* __restrict__ bias, float* __restrict__ C,
    int N, int m0, int n0, int applySigmoid,
    float (*sA)[33], float (*sB)[128])
{
    const int tid = threadIdx.x;
    const int tx = tid & 15;
    const int ty = (tid >> 4) & 15;
    const int arow = (tid >> 3) & 31;
    const int akq  = tid & 7;
    const int brow = (tid >> 5) & 7;
    const int bcol = tid & 31;
    const unsigned sb_base = smem_u32(&sB[0][0]) + tx * 32;

    ull acc2[4][4];
    #pragma unroll
    for (int i = 0; i < 4; i++)
        #pragma unroll
        for (int j = 0; j < 4; j++) acc2[i][j] = 0ULL;

    for (int k0 = 0; k0 < 128; k0 += 32) {
        float4 a0, a1, b0, b1, b2, b3;
        a0 = ldg_cg4(A + (size_t)(m0 + arow     ) * H_ + k0 + akq * 4);
        a1 = ldg_cg4(A + (size_t)(m0 + arow + 32) * H_ + k0 + akq * 4);
        b0 = *(const float4*)(Bm + (size_t)(k0 + brow     ) * N + n0 + bcol * 4);
        b1 = *(const float4*)(Bm + (size_t)(k0 + brow +  8) * N + n0 + bcol * 4);
        b2 = *(const float4*)(Bm + (size_t)(k0 + brow + 16) * N + n0 + bcol * 4);
        b3 = *(const float4*)(Bm + (size_t)(k0 + brow + 24) * N + n0 + bcol * 4);
        __syncthreads();
        sA[arow     ][akq * 4 + 0] = a0.x;  sA[arow     ][akq * 4 + 1] = a0.y;
        sA[arow     ][akq * 4 + 2] = a0.z;  sA[arow     ][akq * 4 + 3] = a0.w;
        sA[arow + 32][akq * 4 + 0] = a1.x;  sA[arow + 32][akq * 4 + 1] = a1.y;
        sA[arow + 32][akq * 4 + 2] = a1.z;  sA[arow + 32][akq * 4 + 3] = a1.w;
        *(float4*)&sB[brow     ][bcol * 4] = b0;
        *(float4*)&sB[brow +  8][bcol * 4] = b1;
        *(float4*)&sB[brow + 16][bcol * 4] = b2;
        *(float4*)&sB[brow + 24][bcol * 4] = b3;
        __syncthreads();

        #pragma unroll
        for (int k = 0; k < 32; k++) {
            ull pa[4];
            #pragma unroll
            for (int i = 0; i < 4; i++) {
                float a = sA[ty * 4 + i][k];
                pa[i] = pk2(a, a);
            }
            ull b01, b23, b45, b67;
            lds_v2u64(sb_base + k * 512,      b01, b23);
            lds_v2u64(sb_base + k * 512 + 16, b45, b67);
            #pragma unroll
            for (int i = 0; i < 4; i++) {
                acc2[i][0] = ffma2(pa[i], b01, acc2[i][0]);
                acc2[i][1] = ffma2(pa[i], b23, acc2[i][1]);
                acc2[i][2] = ffma2(pa[i], b45, acc2[i][2]);
                acc2[i][3] = ffma2(pa[i], b67, acc2[i][3]);
            }
        }
    }

    float bs[8];
    #pragma unroll
    for (int j = 0; j < 8; j++) bs[j] = bias[n0 + tx * 8 + j];
    #pragma unroll
    for (int i = 0; i < 4; i++) {
        const int row = m0 + ty * 4 + i;
        float v[8];
        #pragma unroll
        for (int j = 0; j < 4; j++) unpk2(acc2[i][j], v[2 * j], v[2 * j + 1]);
        #pragma unroll
        for (int j = 0; j < 8; j++) {
            float x = v[j] + bs[j];
            v[j] = applySigmoid ? fsigmoid(x) : x;
        }
        float4 o0 = {v[0], v[1], v[2], v[3]};
        float4 o1 = {v[4], v[5], v[6], v[7]};
        *(float4*)(C + (size_t)row * N + n0 + tx * 8    ) = o0;
        *(float4*)(C + (size_t)row * N + n0 + tx * 8 + 4) = o1;
    }
}

__device__ __forceinline__ void wait_flag(const int* p, int target) {
    if (threadIdx.x == 0) {
        while (ld_acq(p) < target) __nanosleep(128);
    }
    __syncthreads();
}

__global__ void init_flags() {
    const int n = 3 * B_ * NCHUNK;
    int* a = &g_cnt[0][0][0];
    int* b = &g_rdy[0][0][0];
    for (int i = threadIdx.x; i < n; i += blockDim.x) { a[i] = 0; b[i] = 0; }
}

// ---------------------------------------------------------------------------
// Mega-kernel. Scan CTA: 256 threads, 2 lanes per hidden unit u.
//   even lane: z-column (64 FFMA2) + r-column low 8B of each 16B h-chunk (32)
//   odd  lane: h-column (64 FFMA2) + r-column high 8B of each chunk (32)
// -> warp-uniform 96 FFMA2/lane, 8 warps => 768 warp-instr (R8 pipe floor),
// gates exchanged by shfl_xor(1), h double-buffered => ONE barrier/step.
// ---------------------------------------------------------------------------
__global__ void __launch_bounds__(NT, 1) mega(
    const float* __restrict__ X,
    const float* __restrict__ kern,
    const float* __restrict__ rec,
    const float* __restrict__ b_in,
    const float* __restrict__ b_rec,
    const float* __restrict__ W_out,
    const float* __restrict__ b_out,
    float*       __restrict__ out)
{
    __shared__ __align__(16) float hbuf[2][H_];
    __shared__ float sA[64][33];
    __shared__ __align__(16) float sB[32][128];

    const int cta = blockIdx.x;
    const int t   = threadIdx.x;

    if (cta < SCAN_CTAS) {
        const int b    = cta;
        const int lane = t & 31;
        const int odd  = lane & 1;
        const int u    = (t >> 5) * 16 + (lane >> 1);   // hidden unit 0..127
        const int mcol = odd ? (256 + u) : u;           // main column (h / z)
        const int rcol = 128 + u;

        // Weights: main column as 64 packed pairs; r column split per chunk
        // half: even lane takes k=4j..4j+1, odd lane k=4j+2..4j+3.
        ull w2[96];
        #pragma unroll
        for (int j = 0; j < 64; j++)
            w2[j] = pk2(rec[(2 * j) * N3 + mcol], rec[(2 * j + 1) * N3 + mcol]);
        #pragma unroll
        for (int j = 0; j < 32; j++) {
            const int k0 = 4 * j + 2 * odd;
            w2[64 + j] = pk2(rec[k0 * N3 + rcol], rec[(k0 + 1) * N3 + rcol]);
        }
        const float bm  = b_rec[mcol];
        const float brr = b_rec[rcol];

        const unsigned hb   = smem_u32(&hbuf[0][0]);
        const unsigned roff = 8u * (unsigned)odd;

        for (int l = 0; l < 3; l++) {
            float* ybase = ((l == 1) ? g_bufB : g_bufA) + (size_t)b * T_ * H_ + u;
            const float* gp0 = g_gx + (size_t)b * T_ * N3 + mcol;
            const float* gp1 = g_gx + (size_t)b * T_ * N3 + rcol;

            if (t < H_) hbuf[0][t] = 0.f;
            if (t == 0) {
                while (ld_acq(&g_cnt[l][b][0]) < 3) __nanosleep(128);
                while (ld_acq(&g_cnt[l][b][1]) < 3) __nanosleep(128);
            }
            float h_old = 0.f;
            int par = 0;
            __syncthreads();

            float g0v = ldg_cg(gp0);
            float g1v = ldg_cg(gp1);

            for (int step = 0; step < T_; ++step) {
                if ((step & 63) == 0 && step) {
                    const int c  = step >> 6;
                    const int c2 = (c + 1 < NCHUNK) ? c + 1 : NCHUNK - 1;
                    if (t == 0) {
                        while (ld_acq(&g_cnt[l][b][c ]) < 3) __nanosleep(64);
                        while (ld_acq(&g_cnt[l][b][c2]) < 3) __nanosleep(64);
                    }
                    __syncthreads();
                }

                float g0n = ldg_cg(gp0 + (size_t)(step + 1) * N3);
                float g1n = ldg_cg(gp1 + (size_t)(step + 1) * N3);

                // ---- dot: 32 chunks, per chunk 1 LDS.128 + 1 LDS.64 + 3 FFMA2
                const unsigned rb = hb + (unsigned)par * 512u;
                ull aM0 = 0ULL, aM1 = 0ULL, aR = 0ULL;
                #pragma unroll
                for (int j = 0; j < 32; j++) {
                    ull c0, c1, cr;
                    lds_v2u64(rb + 16u * j, c0, c1);
                    lds_u64(rb + 16u * j + roff, cr);
                    aM0 = ffma2(c0, w2[2 * j    ], aM0);
                    aM1 = ffma2(c1, w2[2 * j + 1], aM1);
                    aR  = ffma2(cr, w2[64 + j   ], aR);
                }
                const float dm = sum2(aM0) + sum2(aM1);   // z-dot / h-dot
                const float dr = sum2(aR);                // half of r-dot

                // ---- pair exchange (same warp, lanes 2k/2k+1) ----
                const float drO = __shfl_xor_sync(0xffffffffu, dr, 1);
                const float pre = g0v + dm + bm;          // even: z-pre; odd: gxh+hh+brh
                const float sig = fsigmoid(pre);          // even: z (odd's unused)
                const float zv  = __shfl_xor_sync(0xffffffffu, sig, 1);

                if (odd) {
                    float r    = fsigmoid(dr + drO + g1v + brr);
                    float hhq  = dm + bm;                 // hh + brh
                    float arg  = fminf(fmaf(r, hhq * N2LOG2E, g0v * N2LOG2E), 126.f);
                    float cand = __fdividef(2.f, 1.f + exp2f(arg)) - 1.f;
                    float hn   = fmaf(zv, h_old - cand, cand);
                    h_old = hn;
                    sts_f32(hb + (unsigned)(1 - par) * 512u + 4u * (unsigned)u, hn);
                    ybase[(size_t)step * H_] = hn;
                }
                __syncthreads();     // new h visible; old buffer free
                par ^= 1;
                g0v = g0n;
                g1v = g1n;

                if ((step & 63) == 63) {   // publish chunk for downstream GEMM
                    __threadfence();
                    __syncthreads();
                    if (t == 0) st_rel(&g_rdy[l][b][step >> 6], 1);
                }
            }
        }
    } else {
        // ================= GEMM worker (R8 scheme) =========================
        const int wrk = cta - SCAN_CTAS;

        for (int l = 0; l < 3; l++) {
            const float* Asrc = (l == 0) ? X : ((l == 1) ? g_bufA : g_bufB);
            for (int idx = wrk; idx < NCHUNK * B_ * 3; idx += GEMM_CTAS) {
                const int c = idx / (B_ * 3);
                const int r = idx % (B_ * 3);
                const int b = r / 3;
                const int n = r % 3;
                if (l > 0) wait_flag(&g_rdy[l - 1][b][c], 1);
                gemm_tile(Asrc, kern, b_in, g_gx, N3,
                          b * T_ + c * 64, n * 128, 0, sA, sB);
                __threadfence();
                __syncthreads();
                if (t == 0) red_rel_add1(&g_cnt[l][b][c]);
            }
        }
        for (int idx = wrk; idx < NCHUNK * B_; idx += GEMM_CTAS) {
            const int c = idx / B_;
            const int b = idx % B_;
            wait_flag(&g_rdy[2][b][c], 1);
            gemm_tile(g_bufA, W_out, b_out, out, H_,
                      b * T_ + c * 64, 0, 1, sA, sB);
        }
    }
}

// ---------------------------------------------------------------------------
extern "C" void kernel_launch(void* const* d_in, const int* in_sizes, int n_in,
                              void* d_out, int out_size)
{
    const float* X     = (const float*)d_in[0];
    const float* kern  = (const float*)d_in[1];
    const float* rec   = (const float*)d_in[2];
    const float* b_in  = (const float*)d_in[3];
    const float* b_rec = (const float*)d_in[4];
    const float* W_out = (const float*)d_in[5];
    const float* b_out = (const float*)d_in[6];
    float* out = (float*)d_out;

    init_flags<<<1, 256>>>();
    mega<<<GRID, NT>>>(X, kern, rec, b_in, b_rec, W_out, b_out, out);
}